// round 2
// baseline (speedup 1.0000x reference)
#include <cuda_runtime.h>

// Fixed problem dims
#define NB 4
#define NQv 512
#define MMv 512
#define DDv 256
#define HHv 256

// Scratch (device globals: no allocations allowed)
__device__ float g_q[NB * NQv * HHv];   // projected q, [b*NQ+n][h]
__device__ float g_kT[NB * HHv * MMv];  // projected k, transposed: [b][h][m]

__device__ __forceinline__ float ftanh(float x) {
    float y; asm("tanh.approx.f32 %0, %1;" : "=f"(y) : "f"(x)); return y;
}
__device__ __forceinline__ float fex2(float x) {
    float y; asm("ex2.approx.f32 %0, %1;" : "=f"(y) : "f"(x)); return y;
}
__device__ __forceinline__ unsigned long long pk2(float a, float b) {
    unsigned long long r; asm("mov.b64 %0, {%1, %2};" : "=l"(r) : "f"(a), "f"(b)); return r;
}
__device__ __forceinline__ void fma2(unsigned long long &d, unsigned long long a, unsigned long long b) {
    asm("fma.rn.f32x2 %0, %1, %2, %0;" : "+l"(d) : "l"(a), "l"(b));
}
__device__ __forceinline__ float2 up2(unsigned long long v) {
    float2 r; asm("mov.b64 {%0, %1}, %2;" : "=f"(r.x), "=f"(r.y) : "l"(v)); return r;
}

// ---------------------------------------------------------------------------
// Projection GEMM: C[2048 x 256] = A[2048 x 256] * B[256 x 256]
// trans==0: write g_q[row*256 + col]
// trans==1: write g_kT[(b*256 + col)*512 + m], row = b*512 + m
// Tile 64x64, 256 threads, 4x4 micro-tile, f32x2 FMAs.
// ---------------------------------------------------------------------------
__global__ __launch_bounds__(256) void proj_kernel(const float* __restrict__ A,
                                                   const float* __restrict__ B,
                                                   int trans)
{
    __shared__ __align__(16) float As[16][68];
    __shared__ __align__(16) float Bs[16][64];

    int t = threadIdx.x;
    int tx = t & 15, ty = t >> 4;
    int row0 = (int)(blockIdx.x >> 2) * 64;
    int col0 = (int)(blockIdx.x & 3) * 64;

    int arow = t >> 2, akq = t & 3;   // A-tile load: 64 rows x 4 float4
    int bk = t >> 4, bh = t & 15;     // B-tile load: 16 rows x 16 float4

    unsigned long long acc[4][2];
#pragma unroll
    for (int i = 0; i < 4; i++) { acc[i][0] = 0ull; acc[i][1] = 0ull; }

    for (int k0 = 0; k0 < DDv; k0 += 16) {
        float4 a4 = *(const float4*)(A + (row0 + arow) * DDv + k0 + akq * 4);
        float4 b4 = *(const float4*)(B + (k0 + bk) * HHv + col0 + bh * 4);
        As[akq * 4 + 0][arow] = a4.x;
        As[akq * 4 + 1][arow] = a4.y;
        As[akq * 4 + 2][arow] = a4.z;
        As[akq * 4 + 3][arow] = a4.w;
        *(float4*)&Bs[bk][bh * 4] = b4;
        __syncthreads();
#pragma unroll
        for (int k = 0; k < 16; k++) {
            const unsigned long long* br = (const unsigned long long*)&Bs[k][tx * 4];
            unsigned long long b0 = br[0], b1 = br[1];
#pragma unroll
            for (int i = 0; i < 4; i++) {
                float a = As[k][ty * 4 + i];
                unsigned long long aa = pk2(a, a);
                fma2(acc[i][0], aa, b0);
                fma2(acc[i][1], aa, b1);
            }
        }
        __syncthreads();
    }

#pragma unroll
    for (int i = 0; i < 4; i++) {
        int row = row0 + ty * 4 + i;
        float2 c0 = up2(acc[i][0]);
        float2 c1 = up2(acc[i][1]);
        int col = col0 + tx * 4;
        if (!trans) {
            float4 o = make_float4(c0.x, c0.y, c1.x, c1.y);
            *(float4*)(g_q + row * HHv + col) = o;
        } else {
            int bb = row >> 9, m = row & 511;
            float* base = g_kT + (bb * HHv) * MMv + m;
            base[(col + 0) * MMv] = c0.x;
            base[(col + 1) * MMv] = c0.y;
            base[(col + 2) * MMv] = c1.x;
            base[(col + 3) * MMv] = c1.y;
        }
    }
}

// ---------------------------------------------------------------------------
// Fused scores + softmax + AV.
// Grid: 256 blocks = 4 batches x 64 query-chunks (8 queries each). 256 threads.
// Score phase: thread t owns m = {2t, 2t+1}; 16 accumulators (8q x 2m);
//   h-loop: 1 coalesced LDG.64 of kT + broadcast q/w from smem + 16 tanh.
// Softmax: warp w reduces row w (512 values), exp via ex2.
// AV: m-split 2, v-pair per thread, f32x2 FMAs, smem partial reduce.
// ---------------------------------------------------------------------------
__global__ __launch_bounds__(256) void attn_kernel(const float* __restrict__ Wv,
                                                   const float* __restrict__ value,
                                                   float* __restrict__ out)
{
    __shared__ __align__(16) float qs[HHv][8];
    __shared__ __align__(16) float ws[HHv];
    __shared__ __align__(16) float sc[8][MMv];
    __shared__ __align__(16) float2 ps[2][8][128];
    __shared__ float inv_s[8];

    int t = threadIdx.x;
    int b = (int)(blockIdx.x >> 6);
    int n0 = ((int)blockIdx.x & 63) << 3;
    int w = t >> 5, lane = t & 31;

    // Stage 8 projected-q rows (transposed to [h][q]) + W_v into smem
    {
        const float4* qrow = (const float4*)(g_q + (b * NQv + n0 + w) * HHv);
        float4 v0 = qrow[lane];
        float4 v1 = qrow[lane + 32];
        int h0 = lane * 4;
        qs[h0 + 0][w] = v0.x; qs[h0 + 1][w] = v0.y;
        qs[h0 + 2][w] = v0.z; qs[h0 + 3][w] = v0.w;
        qs[h0 + 128][w] = v1.x; qs[h0 + 129][w] = v1.y;
        qs[h0 + 130][w] = v1.z; qs[h0 + 131][w] = v1.w;
    }
    if (t < 64) ((float4*)ws)[t] = ((const float4*)Wv)[t];
    __syncthreads();

    // ---- Score phase: MUFU.TANH bound ----
    float acc0[8], acc1[8];
#pragma unroll
    for (int i = 0; i < 8; i++) { acc0[i] = 0.f; acc1[i] = 0.f; }

    const float* kbase = g_kT + (b * HHv) * MMv + 2 * t;
#pragma unroll 4
    for (int h = 0; h < HHv; h++) {
        float2 kk = *(const float2*)(kbase + h * MMv);
        float wv = ws[h];
        float4 qa = *(const float4*)&qs[h][0];
        float4 qb = *(const float4*)&qs[h][4];
        float qv[8] = {qa.x, qa.y, qa.z, qa.w, qb.x, qb.y, qb.z, qb.w};
#pragma unroll
        for (int i = 0; i < 8; i++) {
            acc0[i] = fmaf(wv, ftanh(qv[i] + kk.x), acc0[i]);
            acc1[i] = fmaf(wv, ftanh(qv[i] + kk.y), acc1[i]);
        }
    }
#pragma unroll
    for (int i = 0; i < 8; i++)
        ((float2*)sc[i])[t] = make_float2(acc0[i], acc1[i]);
    __syncthreads();

    // ---- Softmax: warp w handles query row w ----
    {
        float vals[16];
        float vmax = -1e30f;
#pragma unroll
        for (int j = 0; j < 16; j++) {
            vals[j] = sc[w][lane + j * 32];
            vmax = fmaxf(vmax, vals[j]);
        }
#pragma unroll
        for (int o = 16; o > 0; o >>= 1)
            vmax = fmaxf(vmax, __shfl_xor_sync(0xffffffffu, vmax, o));
        float sum = 0.f;
#pragma unroll
        for (int j = 0; j < 16; j++) {
            float p = fex2((vals[j] - vmax) * 1.4426950408889634f);
            sc[w][lane + j * 32] = p;
            sum += p;
        }
#pragma unroll
        for (int o = 16; o > 0; o >>= 1)
            sum += __shfl_xor_sync(0xffffffffu, sum, o);
        if (lane == 0) inv_s[w] = 1.0f / sum;
    }
    __syncthreads();

    // ---- AV: out[q,v] = (sum_m p[q,m] * value[m,v]) * inv_sum[q] ----
    int mg = t >> 7;          // m-split group (0 or 1)
    int vg = t & 127;         // v-pair index
    const float* vbase = value + (b * MMv + mg * 256) * DDv + vg * 2;
    unsigned long long acc[8];
#pragma unroll
    for (int q = 0; q < 8; q++) acc[q] = 0ull;
#pragma unroll 4
    for (int mm = 0; mm < 256; mm++) {
        float2 vv = *(const float2*)(vbase + mm * DDv);
        unsigned long long v2 = pk2(vv.x, vv.y);
        int m = mg * 256 + mm;
#pragma unroll
        for (int q = 0; q < 8; q++) {
            float a = sc[q][m];
            fma2(acc[q], pk2(a, a), v2);
        }
    }
#pragma unroll
    for (int q = 0; q < 8; q++) ps[mg][q][vg] = up2(acc[q]);
    __syncthreads();

    // Reduce the 2 m-partials and scale by 1/sum; write out.
    // 8 q x 128 float2 = 1024 elements over 256 threads -> 4 iterations.
#pragma unroll
    for (int r = 0; r < 4; r++) {
        int p = t + r * 256;
        int q = p >> 7, v2i = p & 127;
        float2 s0 = ps[0][q][v2i], s1 = ps[1][q][v2i];
        float iv = inv_s[q];
        float2 o = make_float2((s0.x + s1.x) * iv, (s0.y + s1.y) * iv);
        ((float2*)out)[(b * NQv + n0 + q) * 128 + v2i] = o;
    }
}

extern "C" void kernel_launch(void* const* d_in, const int* in_sizes, int n_in,
                              void* d_out, int out_size)
{
    const float* query = (const float*)d_in[0];
    const float* key   = (const float*)d_in[1];
    const float* value = (const float*)d_in[2];
    const float* Wq    = (const float*)d_in[3];
    const float* Wk    = (const float*)d_in[4];
    const float* Wv    = (const float*)d_in[5];
    float* out = (float*)d_out;

    proj_kernel<<<128, 256>>>(query, Wq, 0);
    proj_kernel<<<128, 256>>>(key,   Wk, 1);
    attn_kernel<<<256, 256>>>(Wv, value, out);
}

// round 3
// speedup vs baseline: 1.1373x; 1.1373x over previous
#include <cuda_runtime.h>

// Fixed problem dims
#define NB 4
#define NQv 512
#define MMv 512
#define DDv 256
#define HHv 256

// Scratch (device globals: no allocations allowed)
__device__ float g_q[NB * NQv * HHv];    // projected q, [b*NQ+n][h]
__device__ float g_kT[NB * HHv * MMv];   // projected k, transposed: [b][h][m]
__device__ float g_sc[NB * NQv * MMv];   // raw scores [b][n][m]

__device__ __forceinline__ float ftanh(float x) {
    float y; asm("tanh.approx.f32 %0, %1;" : "=f"(y) : "f"(x)); return y;
}
__device__ __forceinline__ float fex2(float x) {
    float y; asm("ex2.approx.f32 %0, %1;" : "=f"(y) : "f"(x)); return y;
}
__device__ __forceinline__ unsigned long long pk2(float a, float b) {
    unsigned long long r; asm("mov.b64 %0, {%1, %2};" : "=l"(r) : "f"(a), "f"(b)); return r;
}
__device__ __forceinline__ void fma2(unsigned long long &d, unsigned long long a, unsigned long long b) {
    asm("fma.rn.f32x2 %0, %1, %2, %0;" : "+l"(d) : "l"(a), "l"(b));
}
__device__ __forceinline__ float2 up2(unsigned long long v) {
    float2 r; asm("mov.b64 {%0, %1}, %2;" : "=f"(r.x), "=f"(r.y) : "l"(v)); return r;
}

// ---------------------------------------------------------------------------
// Combined projection GEMM (both q and k in one launch for occupancy):
//   blocks [0,256):  g_q  = query @ W_q        (normal layout)
//   blocks [256,512): g_kT = (key @ W_k)^T     (h-major)
// Tile 32x64, 256 threads, 2x4 micro-tile, f32x2 FMAs.
// ---------------------------------------------------------------------------
__global__ __launch_bounds__(256) void proj_kernel(const float* __restrict__ query,
                                                   const float* __restrict__ key,
                                                   const float* __restrict__ Wq,
                                                   const float* __restrict__ Wk)
{
    __shared__ __align__(16) float As[16][33];   // [k][row], padded
    __shared__ __align__(16) float Bs[16][64];   // [k][col]

    int bid = blockIdx.x;
    int is_k = bid >> 8;
    int local = bid & 255;
    int row0 = (local >> 2) * 32;
    int col0 = (local & 3) * 64;

    const float* A = is_k ? key : query;
    const float* B = is_k ? Wk : Wq;

    int t = threadIdx.x;
    int tx = t & 15, ty = t >> 4;
    int ar = t >> 3, ak = t & 7;      // A load: 32 rows x 8 float2
    int bk = t >> 4, bh = t & 15;     // B load: 16 rows x 16 float4

    unsigned long long acc[2][2];
    acc[0][0] = acc[0][1] = acc[1][0] = acc[1][1] = 0ull;

    for (int k0 = 0; k0 < DDv; k0 += 16) {
        float2 a2 = *(const float2*)(A + (row0 + ar) * DDv + k0 + ak * 2);
        float4 b4 = *(const float4*)(B + (k0 + bk) * HHv + col0 + bh * 4);
        As[ak * 2 + 0][ar] = a2.x;
        As[ak * 2 + 1][ar] = a2.y;
        *(float4*)&Bs[bk][bh * 4] = b4;
        __syncthreads();
#pragma unroll
        for (int k = 0; k < 16; k++) {
            const unsigned long long* br = (const unsigned long long*)&Bs[k][tx * 4];
            unsigned long long b0 = br[0], b1 = br[1];
            float a0 = As[k][ty * 2 + 0];
            float a1 = As[k][ty * 2 + 1];
            fma2(acc[0][0], pk2(a0, a0), b0);
            fma2(acc[0][1], pk2(a0, a0), b1);
            fma2(acc[1][0], pk2(a1, a1), b0);
            fma2(acc[1][1], pk2(a1, a1), b1);
        }
        __syncthreads();
    }

#pragma unroll
    for (int i = 0; i < 2; i++) {
        int row = row0 + ty * 2 + i;
        int col = col0 + tx * 4;
        float2 c0 = up2(acc[i][0]);
        float2 c1 = up2(acc[i][1]);
        if (!is_k) {
            float4 o = make_float4(c0.x, c0.y, c1.x, c1.y);
            *(float4*)(g_q + row * HHv + col) = o;
        } else {
            int bb = row >> 9, m = row & 511;
            float* base = g_kT + (bb * HHv) * MMv + m;
            base[(col + 0) * MMv] = c0.x;
            base[(col + 1) * MMv] = c0.y;
            base[(col + 2) * MMv] = c1.x;
            base[(col + 3) * MMv] = c1.y;
        }
    }
}

// ---------------------------------------------------------------------------
// Score kernel: sc[b,n,m] = sum_h w[h] * tanh(q[b,n,h] + k[b,m,h])
// Tile (8q x 128m), 128 threads (thread owns 1 m, all 8 q).
// Grid = 4b x 64qc x 4mc = 1024 blocks -> ~1% wave imbalance on 148 SMs.
// MUFU.TANH-bound: 268M tanh, floor ~64us.
// ---------------------------------------------------------------------------
__global__ __launch_bounds__(128) void score_kernel(const float* __restrict__ Wv)
{
    __shared__ __align__(16) float qs[8][264];  // [q][h], row stride 16B-aligned
    __shared__ __align__(16) float ws[HHv];

    int t = threadIdx.x;
    int bid = blockIdx.x;
    int mc = bid & 3;
    int qc = (bid >> 2) & 63;
    int b = bid >> 8;
    int n0 = qc * 8;
    int m = mc * 128 + t;

    // Stage 8 projected-q rows + W_v into smem
#pragma unroll
    for (int r = 0; r < 4; r++) {
        int idx = t + r * 128;
        int q = idx >> 6, c4 = idx & 63;
        float4 v = ((const float4*)(g_q + (b * NQv + n0 + q) * HHv))[c4];
        *(float4*)&qs[q][c4 * 4] = v;
    }
    if (t < 64) ((float4*)ws)[t] = ((const float4*)Wv)[t];
    __syncthreads();

    float acc[8];
#pragma unroll
    for (int q = 0; q < 8; q++) acc[q] = 0.f;

    const float* kb = g_kT + (b * HHv) * MMv + m;
#pragma unroll 4
    for (int h = 0; h < HHv; h++) {
        float kv = kb[h * MMv];
        float wv = ws[h];
#pragma unroll
        for (int q = 0; q < 8; q++)
            acc[q] = fmaf(wv, ftanh(qs[q][h] + kv), acc[q]);
    }

#pragma unroll
    for (int q = 0; q < 8; q++)
        g_sc[(b * NQv + n0 + q) * MMv + m] = acc[q];
}

// ---------------------------------------------------------------------------
// Softmax + AV: out[b,n,:] = softmax_m(sc[b,n,:]) @ value[b,:,:]
// Grid 256 = 4b x 64 query-chunks (8q). 256 threads.
// ---------------------------------------------------------------------------
__global__ __launch_bounds__(256) void softav_kernel(const float* __restrict__ value,
                                                     float* __restrict__ out)
{
    __shared__ __align__(16) float sc[8][MMv];
    __shared__ __align__(16) float2 ps[2][8][128];
    __shared__ float inv_s[8];

    int t = threadIdx.x;
    int b = (int)(blockIdx.x >> 6);
    int n0 = ((int)blockIdx.x & 63) << 3;
    int w = t >> 5, lane = t & 31;

    // ---- Softmax: warp w handles query row w, reading scores from global ----
    {
        const float* srow = g_sc + (b * NQv + n0 + w) * MMv;
        float vals[16];
        float vmax = -1e30f;
#pragma unroll
        for (int j = 0; j < 16; j++) {
            vals[j] = srow[lane + j * 32];
            vmax = fmaxf(vmax, vals[j]);
        }
#pragma unroll
        for (int o = 16; o > 0; o >>= 1)
            vmax = fmaxf(vmax, __shfl_xor_sync(0xffffffffu, vmax, o));
        float sum = 0.f;
#pragma unroll
        for (int j = 0; j < 16; j++) {
            float p = fex2((vals[j] - vmax) * 1.4426950408889634f);
            sc[w][lane + j * 32] = p;
            sum += p;
        }
#pragma unroll
        for (int o = 16; o > 0; o >>= 1)
            sum += __shfl_xor_sync(0xffffffffu, sum, o);
        if (lane == 0) inv_s[w] = 1.0f / sum;
    }
    __syncthreads();

    // ---- AV: out[q,v] = (sum_m p[q,m] * value[m,v]) * inv_sum[q] ----
    int mg = t >> 7;          // m-split group (0 or 1)
    int vg = t & 127;         // v-pair index
    const float* vbase = value + (b * MMv + mg * 256) * DDv + vg * 2;
    unsigned long long acc[8];
#pragma unroll
    for (int q = 0; q < 8; q++) acc[q] = 0ull;
#pragma unroll 4
    for (int mm = 0; mm < 256; mm++) {
        float2 vv = *(const float2*)(vbase + mm * DDv);
        unsigned long long v2 = pk2(vv.x, vv.y);
        int m = mg * 256 + mm;
#pragma unroll
        for (int q = 0; q < 8; q++) {
            float a = sc[q][m];
            fma2(acc[q], pk2(a, a), v2);
        }
    }
#pragma unroll
    for (int q = 0; q < 8; q++) ps[mg][q][vg] = up2(acc[q]);
    __syncthreads();

    // Reduce 2 m-partials, scale by 1/sum, write out.
    // 8 q x 128 float2 = 1024 elements over 256 threads -> 4 iterations.
#pragma unroll
    for (int r = 0; r < 4; r++) {
        int p = t + r * 256;
        int q = p >> 7, v2i = p & 127;
        float2 s0 = ps[0][q][v2i], s1 = ps[1][q][v2i];
        float iv = inv_s[q];
        float2 o = make_float2((s0.x + s1.x) * iv, (s0.y + s1.y) * iv);
        ((float2*)out)[(b * NQv + n0 + q) * 128 + v2i] = o;
    }
}

extern "C" void kernel_launch(void* const* d_in, const int* in_sizes, int n_in,
                              void* d_out, int out_size)
{
    const float* query = (const float*)d_in[0];
    const float* key   = (const float*)d_in[1];
    const float* value = (const float*)d_in[2];
    const float* Wq    = (const float*)d_in[3];
    const float* Wk    = (const float*)d_in[4];
    const float* Wv    = (const float*)d_in[5];
    float* out = (float*)d_out;

    proj_kernel<<<512, 256>>>(query, key, Wq, Wk);
    score_kernel<<<1024, 128>>>(Wv);
    softav_kernel<<<256, 256>>>(value, out);
}